// round 17
// baseline (speedup 1.0000x reference)
#include <cuda_runtime.h>

#define PI_F   3.14159265358979f
#define RSQ2_F 0.70710678118654752f
#define N1   512
#define N2   (512*512)
#define HH   256
#define WW   256
#define NA   5
#define NC   12
#define NIMG 60            // NC*NA

#define NX   (NA*HH*WW)    // 327680
#define NM   (NC*HH*WW)    // 786432
#define NK   (NA*NA*N2)    // 6553600
#define CAPG (NIMG*N2)     // scratch capacity in float2

// Scratch (static device globals: allocation-free, graph-safe). 2 x 126 MB.
__device__ float2 g_bufA[CAPG];
__device__ float2 g_bufB[CAPG];

__device__ __forceinline__ float2 cmul(float2 a, float2 b) {
    return make_float2(a.x*b.x - a.y*b.y, a.x*b.y + a.y*b.x);
}
__device__ __forceinline__ float2 cadd(float2 a, float2 b) {
    return make_float2(a.x + b.x, a.y + b.y);
}
__device__ __forceinline__ float2 csub(float2 a, float2 b) {
    return make_float2(a.x - b.x, a.y - b.y);
}
// forward: -i*z ; inverse: +i*z
template<bool INV>
__device__ __forceinline__ float2 rot90(float2 z) {
    return INV ? make_float2(-z.y, z.x) : make_float2(z.y, -z.x);
}
// forward: (1-i)/sqrt2 * z ; inverse: (1+i)/sqrt2 * z
template<bool INV>
__device__ __forceinline__ float2 mul_w1(float2 z) {
    return INV ? make_float2((z.x - z.y)*RSQ2_F, (z.x + z.y)*RSQ2_F)
               : make_float2((z.x + z.y)*RSQ2_F, (z.y - z.x)*RSQ2_F);
}
// forward: -(1+i)/sqrt2 * z ; inverse: (-1+i)/sqrt2 * z
template<bool INV>
__device__ __forceinline__ float2 mul_w3(float2 z) {
    return INV ? make_float2(-(z.x + z.y)*RSQ2_F, (z.x - z.y)*RSQ2_F)
               : make_float2((z.y - z.x)*RSQ2_F, -(z.x + z.y)*RSQ2_F);
}
__device__ __forceinline__ int clampi(int i, int cap) { return i < cap ? i : cap - 1; }

// XOR swizzle on smem float2 index (4-lane interleave).
__device__ __forceinline__ int swz(int pos, int lane) {
    return ((pos << 2) | lane) ^ (((pos >> 3) & 7) << 2);
}

// 8-point DIF butterfly (verified R16, rel_err 5e-7).
template<bool INV>
__device__ __forceinline__ void bfly8(const float2* a, float2* y) {
    float2 t0 = cadd(a[0], a[4]);
    float2 t1 = cadd(a[1], a[5]);
    float2 t2 = cadd(a[2], a[6]);
    float2 t3 = cadd(a[3], a[7]);
    float2 t4 = csub(a[0], a[4]);
    float2 t5 = mul_w1<INV>(csub(a[1], a[5]));
    float2 t6 = rot90<INV>(csub(a[2], a[6]));
    float2 t7 = mul_w3<INV>(csub(a[3], a[7]));
    float2 u0 = cadd(t0, t2);
    float2 u1 = cadd(t1, t3);
    float2 u2 = csub(t0, t2);
    float2 u3 = rot90<INV>(csub(t1, t3));
    float2 u4 = cadd(t4, t6);
    float2 u5 = cadd(t5, t7);
    float2 u6 = csub(t4, t6);
    float2 u7 = rot90<INV>(csub(t5, t7));
    y[0] = cadd(u0, u1);  y[4] = csub(u0, u1);
    y[2] = cadd(u2, u3);  y[6] = csub(u2, u3);
    y[1] = cadd(u4, u5);  y[5] = csub(u4, u5);
    y[3] = cadd(u6, u7);  y[7] = csub(u6, u7);
}

template<bool INV>
__device__ __forceinline__ void fill_tw(float2* tw, int t) {
    #pragma unroll
    for (int i = t; i < 512; i += 256) {
        float s, c;
        __sincosf((INV ? PI_F : -PI_F) * (float)i * (1.0f/256.0f), &s, &c);
        tw[i] = make_float2(c, s);
    }
}

// ---------------------------------------------------------------------------
// Kernel 1: modulate + centered pad + forward row FFT (unchanged from R16).
// ---------------------------------------------------------------------------
__global__ void __launch_bounds__(256) k_row_fwd8(
    const float* __restrict__ xr, const float* __restrict__ xi, int sx,
    const float* __restrict__ mr, const float* __restrict__ mi, int sm_)
{
    __shared__ float2 s0[2048], s1[2048];
    __shared__ float2 tw[512];
    const int t    = threadIdx.x;
    const int lane = t & 3;
    const int j    = t >> 2;               // 0..63
    const int img  = blockIdx.x >> 6;      // c*NA + a
    const int a    = img % NA;
    const int c    = img / NA;
    const int h    = (blockIdx.x & 63) * 4 + lane;

    fill_tw<false>(tw, t);
    __syncthreads();

    float2 av[8], y[8];

    {
        const int bx = a*HH*WW + h*WW;
        const int bm = c*HH*WW + h*WW;
        av[0] = av[1] = av[6] = av[7] = make_float2(0.f, 0.f);
        #pragma unroll
        for (int f = 2; f <= 5; f++) {
            int cix = j + 64*(f - 2);      // 0..255
            int ixx = sx  * (bx + cix);
            int ixm = sm_ * (bm + cix);
            float xvr = xr[ixx], xvi = xi[ixx];
            float mvr = mr[ixm], mvi = mi[ixm];
            av[f] = make_float2(mvr*xvr - mvi*xvi, mvr*xvi + mvi*xvr);
        }
        bfly8<false>(av, y);
        #pragma unroll
        for (int e = 0; e < 8; e++)
            s0[swz(8*j + e, lane)] = cmul(tw[e*j], y[e]);
    }
    __syncthreads();

    {
        const int k  = j & 7;
        const int jm = j - k;
        #pragma unroll
        for (int f = 0; f < 8; f++) av[f] = s0[swz(j + 64*f, lane)];
        bfly8<false>(av, y);
        #pragma unroll
        for (int e = 0; e < 8; e++)
            s1[swz(8*jm + k + 8*e, lane)] = cmul(tw[e*jm], y[e]);
    }
    __syncthreads();

    {
        #pragma unroll
        for (int f = 0; f < 8; f++) av[f] = s1[swz(j + 64*f, lane)];
        bfly8<false>(av, y);
        float2* __restrict__ gout = g_bufA + img * N2 + (128 + h) * N1;
        #pragma unroll
        for (int e = 0; e < 8; e++) gout[j + 64*e] = y[e];
    }
}

// ---------------------------------------------------------------------------
// Kernel 2: forward column FFT (A -> B), unchanged from R16.
// ---------------------------------------------------------------------------
__global__ void __launch_bounds__(256) k_col8_fwd()
{
    __shared__ float2 s0[2048], s1[2048];
    __shared__ float2 tw[512];
    const int t    = threadIdx.x;
    const int lane = t & 3;
    const int j    = t >> 2;
    const int img  = blockIdx.x >> 7;
    const int col0 = (blockIdx.x & 127) * 4;

    fill_tw<false>(tw, t);
    __syncthreads();

    float2 av[8], y[8];
    const float2* __restrict__ gin = g_bufA + img * N2 + col0 + lane;

    {
        av[0] = av[1] = av[6] = av[7] = make_float2(0.f, 0.f);
        av[2] = gin[(j + 128)*N1];
        av[3] = gin[(j + 192)*N1];
        av[4] = gin[(j + 256)*N1];
        av[5] = gin[(j + 320)*N1];
        bfly8<false>(av, y);
        #pragma unroll
        for (int e = 0; e < 8; e++)
            s0[swz(8*j + e, lane)] = cmul(tw[e*j], y[e]);
    }
    __syncthreads();

    {
        const int k  = j & 7;
        const int jm = j - k;
        #pragma unroll
        for (int f = 0; f < 8; f++) av[f] = s0[swz(j + 64*f, lane)];
        bfly8<false>(av, y);
        #pragma unroll
        for (int e = 0; e < 8; e++)
            s1[swz(8*jm + k + 8*e, lane)] = cmul(tw[e*jm], y[e]);
    }
    __syncthreads();

    {
        #pragma unroll
        for (int f = 0; f < 8; f++) av[f] = s1[swz(j + 64*f, lane)];
        bfly8<false>(av, y);
        float2* __restrict__ gout = g_bufB + img * N2 + col0 + lane;
        #pragma unroll
        for (int e = 0; e < 8; e++) gout[(j + 64*e)*N1] = y[e];
    }
}

// ---------------------------------------------------------------------------
// Kernel 3+4 FUSED: frequency mixing + inverse column FFT (B -> A).
// One block = one coil c + 4 columns; loops over the 5 output images ao.
// Stage m=1 computes av[f] = sum_ai K[ao,ai] * Fx[c,ai] straight from gmem
// (Fx re-reads across ao hit L1: 80 KB block working set). Stores only
// rows [128,384). Eliminates the 252 MB combine round-trip.
// ---------------------------------------------------------------------------
__global__ void __launch_bounds__(256) k_col8_mixinv(
    const float* __restrict__ kr, const float* __restrict__ ki, int sk)
{
    __shared__ float2 s0[2048], s1[2048];
    __shared__ float2 tw[512];
    const int t    = threadIdx.x;
    const int lane = t & 3;
    const int j    = t >> 2;               // 0..63
    const int cc   = blockIdx.x >> 7;      // coil 0..11
    const int col0 = (blockIdx.x & 127) * 4;
    const int cp   = col0 + lane;          // column position 0..511

    fill_tw<true>(tw, t);
    __syncthreads();

    float2 av[8], y[8];
    const float2* __restrict__ fx0 = g_bufB + (cc*NA)*N2 + cp;

    #pragma unroll 1
    for (int ao = 0; ao < NA; ao++) {
        // stage m=1 fused with mixing load
        #pragma unroll
        for (int f = 0; f < 8; f++) {
            const int p = (j + 64*f)*N1;
            float2 acc = make_float2(0.f, 0.f);
            #pragma unroll
            for (int ai = 0; ai < NA; ai++) {
                float2 fv = fx0[ai*N2 + p];
                int kidx  = sk * ((ao*NA + ai)*N2 + p + cp);
                float  wr = kr[kidx], wi = ki[kidx];
                acc.x += fv.x*wr - fv.y*wi;
                acc.y += fv.x*wi + fv.y*wr;
            }
            av[f] = acc;
        }
        bfly8<true>(av, y);
        #pragma unroll
        for (int e = 0; e < 8; e++)
            s0[swz(8*j + e, lane)] = cmul(tw[e*j], y[e]);
        __syncthreads();

        // stage m=8
        {
            const int k  = j & 7;
            const int jm = j - k;
            #pragma unroll
            for (int f = 0; f < 8; f++) av[f] = s0[swz(j + 64*f, lane)];
            bfly8<true>(av, y);
            #pragma unroll
            for (int e = 0; e < 8; e++)
                s1[swz(8*jm + k + 8*e, lane)] = cmul(tw[e*jm], y[e]);
        }
        __syncthreads();

        // stage m=64 fused with half store (rows 128..383)
        {
            #pragma unroll
            for (int f = 0; f < 8; f++) av[f] = s1[swz(j + 64*f, lane)];
            bfly8<true>(av, y);
            float2* __restrict__ gout = g_bufA + (cc*NA + ao)*N2 + cp;
            #pragma unroll
            for (int e = 2; e <= 5; e++) gout[(j + 64*e)*N1] = y[e];
        }
        __syncthreads();   // s0/s1 reused by next ao iteration
    }
}

// ---------------------------------------------------------------------------
// Kernel 5: inverse row FFT + crop + scale (unchanged from R16).
// ---------------------------------------------------------------------------
__global__ void __launch_bounds__(256) k_row_inv8()
{
    __shared__ float2 s0[2048], s1[2048];
    __shared__ float2 tw[512];
    const int t    = threadIdx.x;
    const int lane = t & 3;
    const int j    = t >> 2;
    const int img  = blockIdx.x >> 6;
    const int h    = (blockIdx.x & 63) * 4 + lane;

    fill_tw<true>(tw, t);
    __syncthreads();

    float2 av[8], y[8];
    const float2* __restrict__ gin = g_bufA + img * N2 + (128 + h) * N1;

    {
        #pragma unroll
        for (int f = 0; f < 8; f++) av[f] = gin[j + 64*f];
        bfly8<true>(av, y);
        #pragma unroll
        for (int e = 0; e < 8; e++)
            s0[swz(8*j + e, lane)] = cmul(tw[e*j], y[e]);
    }
    __syncthreads();

    {
        const int k  = j & 7;
        const int jm = j - k;
        #pragma unroll
        for (int f = 0; f < 8; f++) av[f] = s0[swz(j + 64*f, lane)];
        bfly8<true>(av, y);
        #pragma unroll
        for (int e = 0; e < 8; e++)
            s1[swz(8*jm + k + 8*e, lane)] = cmul(tw[e*jm], y[e]);
    }
    __syncthreads();

    {
        #pragma unroll
        for (int f = 0; f < 8; f++) av[f] = s1[swz(j + 64*f, lane)];
        bfly8<true>(av, y);
        const float scale = 4.0f / (512.0f * 512.0f);
        float2* __restrict__ gout = g_bufB + img * HH*WW + h * WW;
        #pragma unroll
        for (int e = 2; e <= 5; e++) {
            int ccx = j + 64*e - 128;      // 0..255
            gout[ccx] = make_float2(y[e].x * scale, y[e].y * scale);
        }
    }
}

// ---------------------------------------------------------------------------
// Kernel 6: coil combine, PLANAR float32 output (unchanged, verified).
// ---------------------------------------------------------------------------
__global__ void __launch_bounds__(256) k_final(
    const float* __restrict__ mr, const float* __restrict__ mi, int sm_,
    float* __restrict__ out, int capf)
{
    const int hw = blockIdx.x * 256 + threadIdx.x;
    float2 acc[NA];
    #pragma unroll
    for (int a = 0; a < NA; a++) acc[a] = make_float2(0.f, 0.f);

    for (int c = 0; c < NC; c++) {
        int im = clampi(c*HH*WW + hw, NM);
        float2 m = make_float2(mr[sm_*im], mi[sm_*im]);
        #pragma unroll
        for (int a = 0; a < NA; a++) {
            float2 yv = g_bufB[clampi((c*NA + a)*HH*WW + hw, CAPG)];
            acc[a].x += m.x*yv.x + m.y*yv.y;   // conj(m) * y
            acc[a].y += m.x*yv.y - m.y*yv.x;
        }
    }
    #pragma unroll
    for (int a = 0; a < NA; a++) {
        int idx = a*HH*WW + hw;
        if (idx < capf)      out[idx]      = acc[a].x;
        if (NX + idx < capf) out[NX + idx] = acc[a].y;
    }
}

// ---------------------------------------------------------------------------
extern "C" void kernel_launch(void* const* d_in, const int* in_sizes, int n_in,
                              void* d_out, int out_size)
{
    // Confirmed model (R13/R14/R16 PASSED): dict-order inputs (x_r, x_i,
    // mps_r, mps_i, kern_r, kern_i), real first; sizes as elements (E) or
    // bytes (4E); PLANAR [2,A,H,W] float32 output.
    const float *xr = 0, *xi = 0, *mr = 0, *mi = 0, *kr = 0, *ki = 0;
    int sx = 1, sm_ = 1, sk = 1;

    if (n_in >= 6) {
        for (int i = 0; i < n_in; i++) {
            const float* p = (const float*)d_in[i];
            const long long sz = in_sizes[i];
            if (sz == NX || sz == 4LL*NX)      { if (!xr) xr = p; else if (!xi) xi = p; }
            else if (sz == NM || sz == 4LL*NM) { if (!mr) mr = p; else if (!mi) mi = p; }
            else if (sz == NK || sz == 4LL*NK) { if (!kr) kr = p; else if (!ki) ki = p; }
        }
        if (!xr || !xi || !mr || !mi || !kr || !ki) {
            xr = (const float*)d_in[0]; xi = (const float*)d_in[1];
            mr = (const float*)d_in[2]; mi = (const float*)d_in[3];
            kr = (const float*)d_in[4]; ki = (const float*)d_in[5];
        }
    } else if (n_in >= 3) {
        for (int i = 0; i < 3; i++) {
            const float* p = (const float*)d_in[i];
            const long long sz = in_sizes[i];
            if (sz == NX || sz == 2LL*NX || sz == 8LL*NX)      { xr = p; xi = p + 1; sx = 2; }
            else if (sz == NM || sz == 2LL*NM || sz == 8LL*NM) { mr = p; mi = p + 1; sm_ = 2; }
            else if (sz == NK || sz == 2LL*NK || sz == 8LL*NK) { kr = p; ki = p + 1; sk = 2; }
        }
        if (!xr || !mr || !kr) { return; }
    } else {
        return;
    }

    int capf = (out_size >= 2*NX) ? 2*NX : out_size;

    // 1. modulate + pad + forward row FFT        (-> A rows 128..383)
    k_row_fwd8<<<NIMG * 64, 256>>>(xr, xi, sx, mr, mi, sm_);
    // 2. forward column FFT                      (A -> B, full)
    k_col8_fwd<<<NIMG * 128, 256>>>();
    // 3+4. mixing FUSED with inverse column FFT  (B -> A rows 128..383)
    k_col8_mixinv<<<NC * 128, 256>>>(kr, ki, sk);
    // 5. inverse row FFT + crop + scale          (A -> B front region)
    k_row_inv8<<<NIMG * 64, 256>>>();
    // 6. coil combine (PLANAR output)            (B front + mps -> out)
    k_final<<<HH * WW / 256, 256>>>(mr, mi, sm_, (float*)d_out, capf);
}